// round 1
// baseline (speedup 1.0000x reference)
#include <cuda_runtime.h>
#include <math.h>

// Linear attention (FAVOR-style), fp32 baseline pipeline:
//   1) q' = exp(x @ Wq), k' = exp(x @ Wk)        (GEMM 32768x1024x256, x2)
//   2) zinv[l] = 1/(sum_e q'[l,e] + 1e-8)
//   3) kv[b]   = k'[b]^T @ x[b]                  (per-batch GEMM 256x1024x4096, split-K)
//   4) out     = (q'[b] @ kv[b]) * zinv          (per-batch GEMM 4096x1024x256)

#define BATCH 8
#define LSEQ  4096
#define DDIM  1024
#define EDIM  256
#define BL    (BATCH * LSEQ)      // 32768
#define SPLITK 4

// Scratch (static __device__ arrays per harness rules; no allocation allowed)
__device__ float g_qprime[(size_t)BL * EDIM];                         // 32 MB
__device__ float g_kprime[(size_t)BL * EDIM];                         // 32 MB
__device__ float g_kvpart[(size_t)SPLITK * BATCH * EDIM * DDIM];      // 32 MB
__device__ float g_kv[(size_t)BATCH * EDIM * DDIM];                   // 8 MB
__device__ float g_zinv[BL];

// ---------------------------------------------------------------------------
// Kernel 1: C = exp(X @ W).  X: [BL, DDIM] row-major, W: [DDIM, EDIM] row-major.
// blockIdx.z selects (Wq -> g_qprime) or (Wk -> g_kprime).
// 128x128 tile, BK=8, 256 threads, 8x8 per-thread microtile.
// ---------------------------------------------------------------------------
__global__ __launch_bounds__(256) void proj_exp_kernel(
    const float* __restrict__ x,
    const float* __restrict__ qw,
    const float* __restrict__ kw)
{
    const int BM = 128, BN = 128, BK = 8;
    __shared__ float As[BK][BM];   // A stored K-major (transposed on load)
    __shared__ float Bs[BK][BN];

    const float* W = (blockIdx.z == 0) ? qw : kw;
    float* C = (blockIdx.z == 0) ? g_qprime : g_kprime;

    const int mBase = blockIdx.y * BM;
    const int nBase = blockIdx.x * BN;
    const int tid = threadIdx.x;

    const int aRow = tid >> 1;          // 0..127
    const int aCol = (tid & 1) * 4;     // 0 or 4
    const int bRow = tid >> 5;          // 0..7
    const int bCol = (tid & 31) * 4;    // 0..124
    const int tRow = (tid >> 4) * 8;
    const int tCol = (tid & 15) * 8;

    const float* Aptr = x + (size_t)(mBase + aRow) * DDIM + aCol;
    const float* Bptr = W + (size_t)bRow * EDIM + nBase + bCol;

    float acc[8][8] = {};

    for (int k0 = 0; k0 < DDIM; k0 += BK) {
        float4 a4 = *(const float4*)(Aptr + k0);
        As[aCol + 0][aRow] = a4.x;
        As[aCol + 1][aRow] = a4.y;
        As[aCol + 2][aRow] = a4.z;
        As[aCol + 3][aRow] = a4.w;
        *(float4*)&Bs[bRow][bCol] = *(const float4*)(Bptr + (size_t)k0 * EDIM);
        __syncthreads();

#pragma unroll
        for (int k = 0; k < BK; k++) {
            float4 rm0 = *(const float4*)&As[k][tRow];
            float4 rm1 = *(const float4*)&As[k][tRow + 4];
            float4 rn0 = *(const float4*)&Bs[k][tCol];
            float4 rn1 = *(const float4*)&Bs[k][tCol + 4];
            float rm[8] = {rm0.x, rm0.y, rm0.z, rm0.w, rm1.x, rm1.y, rm1.z, rm1.w};
            float rn[8] = {rn0.x, rn0.y, rn0.z, rn0.w, rn1.x, rn1.y, rn1.z, rn1.w};
#pragma unroll
            for (int i = 0; i < 8; i++)
#pragma unroll
                for (int j = 0; j < 8; j++)
                    acc[i][j] = fmaf(rm[i], rn[j], acc[i][j]);
        }
        __syncthreads();
    }

#pragma unroll
    for (int i = 0; i < 8; i++) {
        float* crow = C + (size_t)(mBase + tRow + i) * EDIM + nBase + tCol;
        float4 v0 = make_float4(expf(acc[i][0]), expf(acc[i][1]),
                                expf(acc[i][2]), expf(acc[i][3]));
        float4 v1 = make_float4(expf(acc[i][4]), expf(acc[i][5]),
                                expf(acc[i][6]), expf(acc[i][7]));
        *(float4*)crow       = v0;
        *(float4*)(crow + 4) = v1;
    }
}

// ---------------------------------------------------------------------------
// Kernel 2: zinv[l] = 1 / (sum_e q'[l,e] + 1e-8).  One warp per row.
// ---------------------------------------------------------------------------
__global__ __launch_bounds__(256) void zinv_kernel()
{
    int warp = (blockIdx.x * blockDim.x + threadIdx.x) >> 5;
    int lane = threadIdx.x & 31;
    if (warp >= BL) return;
    const float* row = g_qprime + (size_t)warp * EDIM;
    float s = 0.0f;
#pragma unroll
    for (int i = 0; i < EDIM / 32; i++) s += row[lane + i * 32];
#pragma unroll
    for (int o = 16; o; o >>= 1) s += __shfl_xor_sync(0xffffffffu, s, o);
    if (lane == 0) g_zinv[warp] = 1.0f / (s + 1e-8f);
}

// ---------------------------------------------------------------------------
// Kernel 3: kv partials. kv[b][e][d] = sum_l k'[b][l][e] * x[b][l][d].
// M=EDIM(e), N=DDIM(d), K=LSEQ(l), split-K by SPLITK into g_kvpart.
// Both operands are naturally K-major (contiguous in m / n), no transpose needed.
// ---------------------------------------------------------------------------
__global__ __launch_bounds__(256) void kv_kernel(const float* __restrict__ x)
{
    const int BM = 128, BN = 128, BK = 8;
    __shared__ float As[BK][BM];
    __shared__ float Bs[BK][BN];

    const int b  = blockIdx.z % BATCH;
    const int ks = blockIdx.z / BATCH;          // 0..SPLITK-1
    const int kLen  = LSEQ / SPLITK;            // 1024
    const int kBase = ks * kLen;

    const int mBase = blockIdx.y * BM;          // e
    const int nBase = blockIdx.x * BN;          // d
    const int tid = threadIdx.x;

    const float* A  = g_kprime + (size_t)b * LSEQ * EDIM;  // [L, E]
    const float* Bx = x        + (size_t)b * LSEQ * DDIM;  // [L, D]

    const int ldRow = tid >> 5;                 // 0..7
    const int ldCol = (tid & 31) * 4;           // 0..124
    const int tRow = (tid >> 4) * 8;
    const int tCol = (tid & 15) * 8;

    float acc[8][8] = {};

    for (int k0 = 0; k0 < kLen; k0 += BK) {
        int l = kBase + k0 + ldRow;
        *(float4*)&As[ldRow][ldCol] = *(const float4*)(A  + (size_t)l * EDIM + mBase + ldCol);
        *(float4*)&Bs[ldRow][ldCol] = *(const float4*)(Bx + (size_t)l * DDIM + nBase + ldCol);
        __syncthreads();

#pragma unroll
        for (int k = 0; k < BK; k++) {
            float4 rm0 = *(const float4*)&As[k][tRow];
            float4 rm1 = *(const float4*)&As[k][tRow + 4];
            float4 rn0 = *(const float4*)&Bs[k][tCol];
            float4 rn1 = *(const float4*)&Bs[k][tCol + 4];
            float rm[8] = {rm0.x, rm0.y, rm0.z, rm0.w, rm1.x, rm1.y, rm1.z, rm1.w};
            float rn[8] = {rn0.x, rn0.y, rn0.z, rn0.w, rn1.x, rn1.y, rn1.z, rn1.w};
#pragma unroll
            for (int i = 0; i < 8; i++)
#pragma unroll
                for (int j = 0; j < 8; j++)
                    acc[i][j] = fmaf(rm[i], rn[j], acc[i][j]);
        }
        __syncthreads();
    }

    float* out = g_kvpart + ((size_t)ks * BATCH + b) * EDIM * DDIM;
#pragma unroll
    for (int i = 0; i < 8; i++) {
        float* crow = out + (size_t)(mBase + tRow + i) * DDIM + nBase + tCol;
        *(float4*)crow       = make_float4(acc[i][0], acc[i][1], acc[i][2], acc[i][3]);
        *(float4*)(crow + 4) = make_float4(acc[i][4], acc[i][5], acc[i][6], acc[i][7]);
    }
}

// ---------------------------------------------------------------------------
// Kernel 4: deterministic split-K reduction of kv partials.
// ---------------------------------------------------------------------------
__global__ __launch_bounds__(256) void kvreduce_kernel()
{
    size_t idx = (size_t)blockIdx.x * blockDim.x + threadIdx.x;
    const size_t n = (size_t)BATCH * EDIM * DDIM;
    if (idx >= n) return;
    float s = 0.0f;
#pragma unroll
    for (int p = 0; p < SPLITK; p++) s += g_kvpart[(size_t)p * n + idx];
    g_kv[idx] = s;
}

// ---------------------------------------------------------------------------
// Kernel 5: out[b][l][d] = zinv[b*L+l] * sum_e q'[b][l][e] * kv[b][e][d].
// M=LSEQ(l), N=DDIM(d), K=EDIM(e).
// ---------------------------------------------------------------------------
__global__ __launch_bounds__(256) void num_kernel(float* __restrict__ out)
{
    const int BM = 128, BN = 128, BK = 8;
    __shared__ float As[BK][BM];
    __shared__ float Bs[BK][BN];

    const int b = blockIdx.z;
    const int mBase = blockIdx.y * BM;          // l
    const int nBase = blockIdx.x * BN;          // d
    const int tid = threadIdx.x;

    const float* A  = g_qprime + (size_t)b * LSEQ * EDIM;  // [L, E] row-major
    const float* Bm = g_kv     + (size_t)b * EDIM * DDIM;  // [E, D] row-major
    float* O = out + (size_t)b * LSEQ * DDIM;

    const int aRow = tid >> 1;
    const int aCol = (tid & 1) * 4;
    const int bRow = tid >> 5;
    const int bCol = (tid & 31) * 4;
    const int tRow = (tid >> 4) * 8;
    const int tCol = (tid & 15) * 8;

    const float* Aptr = A  + (size_t)(mBase + aRow) * EDIM + aCol;
    const float* Bptr = Bm + (size_t)bRow * DDIM + nBase + bCol;

    float acc[8][8] = {};

    for (int k0 = 0; k0 < EDIM; k0 += BK) {
        float4 a4 = *(const float4*)(Aptr + k0);
        As[aCol + 0][aRow] = a4.x;
        As[aCol + 1][aRow] = a4.y;
        As[aCol + 2][aRow] = a4.z;
        As[aCol + 3][aRow] = a4.w;
        *(float4*)&Bs[bRow][bCol] = *(const float4*)(Bptr + (size_t)k0 * DDIM);
        __syncthreads();

#pragma unroll
        for (int k = 0; k < BK; k++) {
            float4 rm0 = *(const float4*)&As[k][tRow];
            float4 rm1 = *(const float4*)&As[k][tRow + 4];
            float4 rn0 = *(const float4*)&Bs[k][tCol];
            float4 rn1 = *(const float4*)&Bs[k][tCol + 4];
            float rm[8] = {rm0.x, rm0.y, rm0.z, rm0.w, rm1.x, rm1.y, rm1.z, rm1.w};
            float rn[8] = {rn0.x, rn0.y, rn0.z, rn0.w, rn1.x, rn1.y, rn1.z, rn1.w};
#pragma unroll
            for (int i = 0; i < 8; i++)
#pragma unroll
                for (int j = 0; j < 8; j++)
                    acc[i][j] = fmaf(rm[i], rn[j], acc[i][j]);
        }
        __syncthreads();
    }

#pragma unroll
    for (int i = 0; i < 8; i++) {
        float z = g_zinv[b * LSEQ + mBase + tRow + i];
        float* crow = O + (size_t)(mBase + tRow + i) * DDIM + nBase + tCol;
        *(float4*)crow       = make_float4(acc[i][0] * z, acc[i][1] * z,
                                           acc[i][2] * z, acc[i][3] * z);
        *(float4*)(crow + 4) = make_float4(acc[i][4] * z, acc[i][5] * z,
                                           acc[i][6] * z, acc[i][7] * z);
    }
}

// ---------------------------------------------------------------------------
extern "C" void kernel_launch(void* const* d_in, const int* in_sizes, int n_in,
                              void* d_out, int out_size)
{
    const float* x  = (const float*)d_in[0];
    const float* qw = (const float*)d_in[1];
    const float* kw = (const float*)d_in[2];
    float* out = (float*)d_out;

    dim3 gA(EDIM / 128, BL / 128, 2);            // 2 x 256 x 2
    proj_exp_kernel<<<gA, 256>>>(x, qw, kw);

    zinv_kernel<<<BL / 8, 256>>>();              // 8 rows per 256-thread block

    dim3 gB(DDIM / 128, EDIM / 128, BATCH * SPLITK);  // 8 x 2 x 32
    kv_kernel<<<gB, 256>>>(x);

    const int nkv = BATCH * EDIM * DDIM;
    kvreduce_kernel<<<(nkv + 255) / 256, 256>>>();

    dim3 gC(DDIM / 128, LSEQ / 128, BATCH);      // 8 x 32 x 8
    num_kernel<<<gC, 256>>>(out);
}

// round 7
// speedup vs baseline: 2.6796x; 2.6796x over previous
#include <cuda_runtime.h>
#include <cuda_fp16.h>
#include <mma.h>
#include <math.h>
#include <stdint.h>

using namespace nvcuda;

// Linear attention. R1's passing 5-kernel structure and fp32 global dataflow,
// with the inner GEMM math swapped from FFMA to wmma m16n16k16 (fp16 in, fp32
// acc) using 3xFP16 hi/lo splitting done during the smem fill.
//   proj: acc = X @ (256 W); q'' = exp(acc/256)/256   -> g_q / g_k (fp32)
//   kv  : acc = (16 k'')^T @ x = kv/16                -> g_kv (fp32)
//   num : acc = (16 q'') @ (kv/16) = num/256          -> out (raw)
//   out *= 256/(256*sum(q'') + 1e-8)
// All scale factors are exact powers of two.

#define BATCH 8
#define LSEQ  4096
#define DDIM  1024
#define EDIM  256
#define BL    (BATCH * LSEQ)
#define SP    136   // padded smem row length (halves): 128 + 8

// ---- fp32 scratch only (mirrors R1, which passed) ----
__device__ float g_q [(size_t)BL * EDIM];                 // q'' = q'/256
__device__ float g_k [(size_t)BL * EDIM];                 // k'' = k'/256
__device__ float g_kv[(size_t)BATCH * EDIM * DDIM];       // kv/16
__device__ float g_zinv[BL];

// ---------------------------------------------------------------------------
// smem fills: read fp32 global, scale, split into hi/lo fp16.
// Tiles are [32 k][128 mn] with row pitch SP halves.
// ---------------------------------------------------------------------------
// direct: global src laid out [k][n] (n contiguous), src pre-offset to (k0, n0).
__device__ __forceinline__ void fill_direct(__half* dh, __half* dl,
                                            const float* __restrict__ src,
                                            size_t stride, float scale, int tid) {
#pragma unroll
    for (int r = 0; r < 4; r++) {
        int k = r * 8 + (tid >> 5);
        int n = (tid & 31) * 4;
        float4 v = *(const float4*)(src + (size_t)k * stride + n);
        float x0 = v.x * scale, x1 = v.y * scale, x2 = v.z * scale, x3 = v.w * scale;
        __half h0 = __float2half_rn(x0), h1 = __float2half_rn(x1);
        __half h2 = __float2half_rn(x2), h3 = __float2half_rn(x3);
        __half l0 = __float2half_rn(x0 - __half2float(h0));
        __half l1 = __float2half_rn(x1 - __half2float(h1));
        __half l2 = __float2half_rn(x2 - __half2float(h2));
        __half l3 = __float2half_rn(x3 - __half2float(h3));
        __half* ph = dh + k * SP + n;
        __half* pl = dl + k * SP + n;
        *(__half2*)(ph)     = __halves2half2(h0, h1);
        *(__half2*)(ph + 2) = __halves2half2(h2, h3);
        *(__half2*)(pl)     = __halves2half2(l0, l1);
        *(__half2*)(pl + 2) = __halves2half2(l2, l3);
    }
}
// transpose: global src laid out [m][k] (k contiguous), src pre-offset to (m0, k0).
__device__ __forceinline__ void fill_trans(__half* dh, __half* dl,
                                           const float* __restrict__ src,
                                           size_t stride, float scale, int tid) {
#pragma unroll
    for (int r = 0; r < 4; r++) {
        int m = r * 32 + (tid >> 3);
        int k = (tid & 7) * 4;
        float4 v = *(const float4*)(src + (size_t)m * stride + k);
        float x0 = v.x * scale, x1 = v.y * scale, x2 = v.z * scale, x3 = v.w * scale;
        __half h0 = __float2half_rn(x0), h1 = __float2half_rn(x1);
        __half h2 = __float2half_rn(x2), h3 = __float2half_rn(x3);
        dh[(k + 0) * SP + m] = h0;
        dh[(k + 1) * SP + m] = h1;
        dh[(k + 2) * SP + m] = h2;
        dh[(k + 3) * SP + m] = h3;
        dl[(k + 0) * SP + m] = __float2half_rn(x0 - __half2float(h0));
        dl[(k + 1) * SP + m] = __float2half_rn(x1 - __half2float(h1));
        dl[(k + 2) * SP + m] = __float2half_rn(x2 - __half2float(h2));
        dl[(k + 3) * SP + m] = __float2half_rn(x3 - __half2float(h3));
    }
}

// one BK=32 step: acc += Ah*Bh + Ah*Bl + Al*Bh on the 128x128 tile
__device__ __forceinline__ void wmma_step(
    const __half* As_h, const __half* As_l,
    const __half* Bs_h, const __half* Bs_l,
    wmma::fragment<wmma::accumulator, 16, 16, 16, float> acc[4][2],
    int warpM, int warpN)
{
#pragma unroll
    for (int kk = 0; kk < 32; kk += 16) {
        wmma::fragment<wmma::matrix_a, 16, 16, 16, __half, wmma::col_major> a_h[4], a_l[4];
        wmma::fragment<wmma::matrix_b, 16, 16, 16, __half, wmma::row_major> b_h[2], b_l[2];
#pragma unroll
        for (int mi = 0; mi < 4; mi++) {
            int m0 = warpM * 64 + mi * 16;
            wmma::load_matrix_sync(a_h[mi], As_h + kk * SP + m0, SP);
            wmma::load_matrix_sync(a_l[mi], As_l + kk * SP + m0, SP);
        }
#pragma unroll
        for (int nj = 0; nj < 2; nj++) {
            int n0 = warpN * 32 + nj * 16;
            wmma::load_matrix_sync(b_h[nj], Bs_h + kk * SP + n0, SP);
            wmma::load_matrix_sync(b_l[nj], Bs_l + kk * SP + n0, SP);
        }
#pragma unroll
        for (int mi = 0; mi < 4; mi++)
#pragma unroll
            for (int nj = 0; nj < 2; nj++) {
                wmma::mma_sync(acc[mi][nj], a_h[mi], b_h[nj], acc[mi][nj]);
                wmma::mma_sync(acc[mi][nj], a_h[mi], b_l[nj], acc[mi][nj]);
                wmma::mma_sync(acc[mi][nj], a_l[mi], b_h[nj], acc[mi][nj]);
            }
    }
}

// ---------------------------------------------------------------------------
// Kernel 1: proj. grid (EDIM/128, BL/128, 2). C tile = X @ (256 W), epi exp.
// ---------------------------------------------------------------------------
__global__ __launch_bounds__(256, 1) void proj_kernel(
    const float* __restrict__ x,
    const float* __restrict__ qw,
    const float* __restrict__ kw)
{
    __shared__ __align__(32) __half As_h[32 * SP], As_l[32 * SP];
    __shared__ __align__(32) __half Bs_h[32 * SP], Bs_l[32 * SP];
    const int tid = threadIdx.x;
    const int warpM = (tid >> 5) >> 2, warpN = (tid >> 5) & 3;
    const int mBase = blockIdx.y * 128, nBase = blockIdx.x * 128;
    const float* W = blockIdx.z ? kw : qw;
    float* C = blockIdx.z ? g_k : g_q;

    wmma::fragment<wmma::accumulator, 16, 16, 16, float> acc[4][2];
#pragma unroll
    for (int mi = 0; mi < 4; mi++)
#pragma unroll
        for (int nj = 0; nj < 2; nj++) wmma::fill_fragment(acc[mi][nj], 0.0f);

    for (int t = 0; t < DDIM / 32; t++) {
        int k0 = t * 32;
        fill_trans(As_h, As_l, x + (size_t)mBase * DDIM + k0, DDIM, 1.0f, tid);
        fill_direct(Bs_h, Bs_l, W + (size_t)k0 * EDIM + nBase, EDIM, 256.0f, tid);
        __syncthreads();
        wmma_step(As_h, As_l, Bs_h, Bs_l, acc, warpM, warpN);
        __syncthreads();
    }

    const float is = 1.0f / 256.0f;
#pragma unroll
    for (int mi = 0; mi < 4; mi++)
#pragma unroll
        for (int nj = 0; nj < 2; nj++) {
#pragma unroll
            for (int e = 0; e < acc[mi][nj].num_elements; e++)
                acc[mi][nj].x[e] = expf(acc[mi][nj].x[e] * is) * is;
            wmma::store_matrix_sync(
                C + (size_t)(mBase + warpM * 64 + mi * 16) * EDIM
                  + nBase + warpN * 32 + nj * 16,
                acc[mi][nj], EDIM, wmma::mem_row_major);
        }
}

// ---------------------------------------------------------------------------
// Kernel 2: zinv. One warp per row of g_q.  Z = 256/(256*s + 1e-8).
// ---------------------------------------------------------------------------
__global__ __launch_bounds__(256) void zinv_kernel()
{
    int row = (int)((blockIdx.x * 256 + threadIdx.x) >> 5);
    int lane = threadIdx.x & 31;
    const float* r = g_q + (size_t)row * EDIM;
    float s = 0.0f;
#pragma unroll
    for (int i = 0; i < EDIM / 32; i++) s += r[lane + i * 32];
#pragma unroll
    for (int o = 16; o; o >>= 1) s += __shfl_xor_sync(0xffffffffu, s, o);
    if (lane == 0) g_zinv[row] = 256.0f / (256.0f * s + 1e-8f);
}

// ---------------------------------------------------------------------------
// Kernel 3: kv. grid (DDIM/128, EDIM/128, BATCH). acc = (16 k'')^T @ x.
// A smem from g_k [l][e] (direct: k=l rows contiguous in e=m), B from x [l][d].
// ---------------------------------------------------------------------------
__global__ __launch_bounds__(256, 1) void kv_kernel(const float* __restrict__ x)
{
    __shared__ __align__(32) __half As_h[32 * SP], As_l[32 * SP];
    __shared__ __align__(32) __half Bs_h[32 * SP], Bs_l[32 * SP];
    const int tid = threadIdx.x;
    const int warpM = (tid >> 5) >> 2, warpN = (tid >> 5) & 3;
    const int b = blockIdx.z;
    const int mBase = blockIdx.y * 128;   // e
    const int nBase = blockIdx.x * 128;   // d
    const float* A  = g_k + (size_t)b * LSEQ * EDIM;
    const float* Bx = x   + (size_t)b * LSEQ * DDIM;

    wmma::fragment<wmma::accumulator, 16, 16, 16, float> acc[4][2];
#pragma unroll
    for (int mi = 0; mi < 4; mi++)
#pragma unroll
        for (int nj = 0; nj < 2; nj++) wmma::fill_fragment(acc[mi][nj], 0.0f);

    for (int t = 0; t < LSEQ / 32; t++) {
        int k0 = t * 32;
        fill_direct(As_h, As_l, A  + (size_t)k0 * EDIM + mBase, EDIM, 16.0f, tid);
        fill_direct(Bs_h, Bs_l, Bx + (size_t)k0 * DDIM + nBase, DDIM, 1.0f,  tid);
        __syncthreads();
        wmma_step(As_h, As_l, Bs_h, Bs_l, acc, warpM, warpN);
        __syncthreads();
    }

    float* C = g_kv + (size_t)b * EDIM * DDIM;
#pragma unroll
    for (int mi = 0; mi < 4; mi++)
#pragma unroll
        for (int nj = 0; nj < 2; nj++)
            wmma::store_matrix_sync(
                C + (size_t)(mBase + warpM * 64 + mi * 16) * DDIM
                  + nBase + warpN * 32 + nj * 16,
                acc[mi][nj], DDIM, wmma::mem_row_major);
}

// ---------------------------------------------------------------------------
// Kernel 4: num. grid (DDIM/128, LSEQ/128, BATCH). acc = (16 q'') @ (kv/16).
// A from g_q [l][e] (transpose fill), B from g_kv [e][d] (direct).
// ---------------------------------------------------------------------------
__global__ __launch_bounds__(256, 1) void num_kernel(float* __restrict__ out)
{
    __shared__ __align__(32) __half As_h[32 * SP], As_l[32 * SP];
    __shared__ __align__(32) __half Bs_h[32 * SP], Bs_l[32 * SP];
    const int tid = threadIdx.x;
    const int warpM = (tid >> 5) >> 2, warpN = (tid >> 5) & 3;
    const int b = blockIdx.z;
    const int mBase = blockIdx.y * 128;   // l
    const int nBase = blockIdx.x * 128;   // d
    const float* A  = g_q  + ((size_t)b * LSEQ + mBase) * EDIM;
    const float* Bk = g_kv + (size_t)b * EDIM * DDIM;

    wmma::fragment<wmma::accumulator, 16, 16, 16, float> acc[4][2];
#pragma unroll
    for (int mi = 0; mi < 4; mi++)
#pragma unroll
        for (int nj = 0; nj < 2; nj++) wmma::fill_fragment(acc[mi][nj], 0.0f);

    for (int t = 0; t < EDIM / 32; t++) {
        int k0 = t * 32;
        fill_trans(As_h, As_l, A + k0, EDIM, 16.0f, tid);
        fill_direct(Bs_h, Bs_l, Bk + (size_t)k0 * DDIM + nBase, DDIM, 1.0f, tid);
        __syncthreads();
        wmma_step(As_h, As_l, Bs_h, Bs_l, acc, warpM, warpN);
        __syncthreads();
    }

    float* O = out + (size_t)b * LSEQ * DDIM;
#pragma unroll
    for (int mi = 0; mi < 4; mi++)
#pragma unroll
        for (int nj = 0; nj < 2; nj++)
            wmma::store_matrix_sync(
                O + (size_t)(mBase + warpM * 64 + mi * 16) * DDIM
                  + nBase + warpN * 32 + nj * 16,
                acc[mi][nj], DDIM, wmma::mem_row_major);
}

// ---------------------------------------------------------------------------
// Kernel 5: out[l][d] *= zinv[l]
// ---------------------------------------------------------------------------
__global__ __launch_bounds__(256) void scale_out(float4* __restrict__ out)
{
    size_t i = (size_t)blockIdx.x * 256 + threadIdx.x;   // over BL*DDIM/4
    float z = g_zinv[(i * 4) / DDIM];
    float4 v = out[i];
    out[i] = make_float4(v.x * z, v.y * z, v.z * z, v.w * z);
}

// ---------------------------------------------------------------------------
extern "C" void kernel_launch(void* const* d_in, const int* in_sizes, int n_in,
                              void* d_out, int out_size)
{
    const float* x  = (const float*)d_in[0];
    const float* qw = (const float*)d_in[1];
    const float* kw = (const float*)d_in[2];
    float* out = (float*)d_out;

    proj_kernel<<<dim3(EDIM / 128, BL / 128, 2), 256>>>(x, qw, kw);
    zinv_kernel<<<BL / 8, 256>>>();
    kv_kernel<<<dim3(DDIM / 128, EDIM / 128, BATCH), 256>>>(x);
    num_kernel<<<dim3(DDIM / 128, LSEQ / 128, BATCH), 256>>>(out);
    scale_out<<<(int)((size_t)BL * DDIM / 4 / 256), 256>>>((float4*)out);
}

// round 8
// speedup vs baseline: 3.5152x; 1.3118x over previous
#include <cuda_runtime.h>
#include <cuda_fp16.h>
#include <mma.h>
#include <math.h>
#include <stdint.h>

using namespace nvcuda;

// Linear attention, wmma m16n16k16 (fp16 in, fp32 acc), 3xFP16 hi/lo splitting
// done during smem fill. R8: register-staged double-buffered pipeline (BK=16,
// one sync/iter) + zinv folded into g_q (scale_out kernel removed).
//   proj: acc = X @ (256 W); q''=exp(acc/256)/256 -> g_q/g_k
//   zinv: Z = 256/(256*sum(q''row)+1e-8); g_q row *= Z
//   kv  : g_kv = (16 k'')^T @ x            (= kv_true/16)
//   num : out  = (16 q''Z) @ g_kv          (= q''*Z*kv_true, final)

#define BATCH 8
#define LSEQ  4096
#define DDIM  1024
#define EDIM  256
#define BL    (BATCH * LSEQ)
#define SP    136            // padded smem row pitch (halves)
#define TILE  (16 * SP)      // one [16 k][128 mn] tile

// ---- fp32 scratch ----
__device__ float g_q [(size_t)BL * EDIM];             // q''  (later *= Z)
__device__ float g_k [(size_t)BL * EDIM];             // k''
__device__ float g_kv[(size_t)BATCH * EDIM * DDIM];   // kv_true / 16

// ---------------------------------------------------------------------------
// fills: ld (global fp32 -> regs), st (regs -> scaled hi/lo fp16 smem)
// direct: src is [k][n], n contiguous;  trans: src is [m][k], k contiguous.
// ---------------------------------------------------------------------------
__device__ __forceinline__ void ld_direct(float4 v[2], const float* __restrict__ src,
                                          size_t stride, int tid) {
#pragma unroll
    for (int r = 0; r < 2; r++) {
        int k = r * 8 + (tid >> 5), n = (tid & 31) * 4;
        v[r] = *(const float4*)(src + (size_t)k * stride + n);
    }
}
__device__ __forceinline__ void st_split(__half* dh, __half* dl, int idx, float x) {
    __half h = __float2half_rn(x);
    dh[idx] = h;
    dl[idx] = __float2half_rn(x - __half2float(h));
}
__device__ __forceinline__ void st_direct(__half* dh, __half* dl, const float4 v[2],
                                          float scale, int tid) {
#pragma unroll
    for (int r = 0; r < 2; r++) {
        int k = r * 8 + (tid >> 5), n = (tid & 31) * 4;
        st_split(dh, dl, k * SP + n + 0, v[r].x * scale);
        st_split(dh, dl, k * SP + n + 1, v[r].y * scale);
        st_split(dh, dl, k * SP + n + 2, v[r].z * scale);
        st_split(dh, dl, k * SP + n + 3, v[r].w * scale);
    }
}
__device__ __forceinline__ void ld_trans(float4 v[2], const float* __restrict__ src,
                                         size_t stride, int tid) {
#pragma unroll
    for (int r = 0; r < 2; r++) {
        int m = r * 64 + (tid >> 2), k = (tid & 3) * 4;
        v[r] = *(const float4*)(src + (size_t)m * stride + k);
    }
}
__device__ __forceinline__ void st_trans(__half* dh, __half* dl, const float4 v[2],
                                         float scale, int tid) {
#pragma unroll
    for (int r = 0; r < 2; r++) {
        int m = r * 64 + (tid >> 2), k = (tid & 3) * 4;
        st_split(dh, dl, (k + 0) * SP + m, v[r].x * scale);
        st_split(dh, dl, (k + 1) * SP + m, v[r].y * scale);
        st_split(dh, dl, (k + 2) * SP + m, v[r].z * scale);
        st_split(dh, dl, (k + 3) * SP + m, v[r].w * scale);
    }
}

// one BK=16 step: acc += Ah*Bh + Ah*Bl + Al*Bh
__device__ __forceinline__ void step16(
    const __half* Ah, const __half* Al, const __half* Bh, const __half* Bl,
    wmma::fragment<wmma::accumulator, 16, 16, 16, float> acc[4][2],
    int warpM, int warpN)
{
    wmma::fragment<wmma::matrix_a, 16, 16, 16, __half, wmma::col_major> ah[4], al[4];
    wmma::fragment<wmma::matrix_b, 16, 16, 16, __half, wmma::row_major> bh[2], bl[2];
#pragma unroll
    for (int mi = 0; mi < 4; mi++) {
        int m0 = warpM * 64 + mi * 16;
        wmma::load_matrix_sync(ah[mi], Ah + m0, SP);
        wmma::load_matrix_sync(al[mi], Al + m0, SP);
    }
#pragma unroll
    for (int nj = 0; nj < 2; nj++) {
        int n0 = warpN * 32 + nj * 16;
        wmma::load_matrix_sync(bh[nj], Bh + n0, SP);
        wmma::load_matrix_sync(bl[nj], Bl + n0, SP);
    }
#pragma unroll
    for (int mi = 0; mi < 4; mi++)
#pragma unroll
        for (int nj = 0; nj < 2; nj++) {
            wmma::mma_sync(acc[mi][nj], ah[mi], bh[nj], acc[mi][nj]);
            wmma::mma_sync(acc[mi][nj], ah[mi], bl[nj], acc[mi][nj]);
            wmma::mma_sync(acc[mi][nj], al[mi], bh[nj], acc[mi][nj]);
        }
}

// smem: [stage][tile: Ah, Al, Bh, Bl]
#define DECL_SMEM  __shared__ __align__(32) __half S[2][4][TILE]

// Pipelined loop. LD_A/ST_A use trans or direct per kernel via macros below.
#define PIPELINE(NK, LD_A, ST_A, LD_B, ST_B)                                   \
    {                                                                          \
        float4 vA[2], vB[2];                                                   \
        LD_A(0); LD_B(0);                                                      \
        ST_A(0); ST_B(0);                                                      \
        __syncthreads();                                                       \
        for (int t = 0; t < (NK); t++) {                                       \
            if (t + 1 < (NK)) { LD_A(t + 1); LD_B(t + 1); }                    \
            int s = t & 1;                                                     \
            step16(S[s][0], S[s][1], S[s][2], S[s][3], acc, warpM, warpN);     \
            if (t + 1 < (NK)) {                                                \
                int s2 = (t + 1) & 1;                                          \
                ST_A(s2_dummy_##__LINE__); (void)0;                            \
            }                                                                  \
            __syncthreads();                                                   \
        }                                                                      \
    }

// (macro gymnastics are error-prone — write the loops explicitly instead)

// ---------------------------------------------------------------------------
// Kernel 1: proj. grid (EDIM/128, BL/128, 2).  acc = X @ (256 W), epi exp.
// ---------------------------------------------------------------------------
__global__ __launch_bounds__(256, 1) void proj_kernel(
    const float* __restrict__ x,
    const float* __restrict__ qw,
    const float* __restrict__ kw)
{
    DECL_SMEM;
    const int tid = threadIdx.x;
    const int warpM = (tid >> 5) >> 2, warpN = (tid >> 5) & 3;
    const int mBase = blockIdx.y * 128, nBase = blockIdx.x * 128;
    const float* W = blockIdx.z ? kw : qw;
    float* C = blockIdx.z ? g_k : g_q;
    const float* Ag = x + (size_t)mBase * DDIM;   // [m][k], +t*16 on k
    const float* Bg = W + nBase;                  // [k][n], +t*16*EDIM

    wmma::fragment<wmma::accumulator, 16, 16, 16, float> acc[4][2];
#pragma unroll
    for (int mi = 0; mi < 4; mi++)
#pragma unroll
        for (int nj = 0; nj < 2; nj++) wmma::fill_fragment(acc[mi][nj], 0.0f);

    const int NK = DDIM / 16;
    float4 vA[2], vB[2];
    ld_trans(vA, Ag, DDIM, tid);
    ld_direct(vB, Bg, EDIM, tid);
    st_trans(S[0][0], S[0][1], vA, 1.0f, tid);
    st_direct(S[0][2], S[0][3], vB, 256.0f, tid);
    __syncthreads();
    for (int t = 0; t < NK; t++) {
        if (t + 1 < NK) {
            ld_trans(vA, Ag + (t + 1) * 16, DDIM, tid);
            ld_direct(vB, Bg + (size_t)(t + 1) * 16 * EDIM, EDIM, tid);
        }
        int s = t & 1;
        step16(S[s][0], S[s][1], S[s][2], S[s][3], acc, warpM, warpN);
        if (t + 1 < NK) {
            int s2 = (t + 1) & 1;
            st_trans(S[s2][0], S[s2][1], vA, 1.0f, tid);
            st_direct(S[s2][2], S[s2][3], vB, 256.0f, tid);
        }
        __syncthreads();
    }

    const float is = 1.0f / 256.0f;
#pragma unroll
    for (int mi = 0; mi < 4; mi++)
#pragma unroll
        for (int nj = 0; nj < 2; nj++) {
#pragma unroll
            for (int e = 0; e < acc[mi][nj].num_elements; e++)
                acc[mi][nj].x[e] = expf(acc[mi][nj].x[e] * is) * is;
            wmma::store_matrix_sync(
                C + (size_t)(mBase + warpM * 64 + mi * 16) * EDIM
                  + nBase + warpN * 32 + nj * 16,
                acc[mi][nj], EDIM, wmma::mem_row_major);
        }
}

// ---------------------------------------------------------------------------
// Kernel 2: zinv + fold into q. One warp per row.
// ---------------------------------------------------------------------------
__global__ __launch_bounds__(256) void zinv_kernel()
{
    int row = (int)((blockIdx.x * 256 + threadIdx.x) >> 5);
    int lane = threadIdx.x & 31;
    float* r = g_q + (size_t)row * EDIM;
    float s = 0.0f;
#pragma unroll
    for (int i = 0; i < EDIM / 32; i++) s += r[lane + i * 32];
#pragma unroll
    for (int o = 16; o; o >>= 1) s += __shfl_xor_sync(0xffffffffu, s, o);
    float Z = 256.0f / (256.0f * s + 1e-8f);
#pragma unroll
    for (int i = 0; i < EDIM / 32; i++) r[lane + i * 32] *= Z;
}

// ---------------------------------------------------------------------------
// Kernel 3: kv. grid (DDIM/128, EDIM/128, BATCH).  acc = (16 k'')^T @ x.
// ---------------------------------------------------------------------------
__global__ __launch_bounds__(256, 1) void kv_kernel(const float* __restrict__ x)
{
    DECL_SMEM;
    const int tid = threadIdx.x;
    const int warpM = (tid >> 5) >> 2, warpN = (tid >> 5) & 3;
    const int b = blockIdx.z;
    const int mBase = blockIdx.y * 128;   // e
    const int nBase = blockIdx.x * 128;   // d
    const float* Ag = g_k + (size_t)b * LSEQ * EDIM + mBase;  // [l][e] direct
    const float* Bg = x   + (size_t)b * LSEQ * DDIM + nBase;  // [l][d] direct

    wmma::fragment<wmma::accumulator, 16, 16, 16, float> acc[4][2];
#pragma unroll
    for (int mi = 0; mi < 4; mi++)
#pragma unroll
        for (int nj = 0; nj < 2; nj++) wmma::fill_fragment(acc[mi][nj], 0.0f);

    const int NK = LSEQ / 16;
    float4 vA[2], vB[2];
    ld_direct(vA, Ag, EDIM, tid);
    ld_direct(vB, Bg, DDIM, tid);
    st_direct(S[0][0], S[0][1], vA, 16.0f, tid);
    st_direct(S[0][2], S[0][3], vB, 1.0f, tid);
    __syncthreads();
    for (int t = 0; t < NK; t++) {
        if (t + 1 < NK) {
            ld_direct(vA, Ag + (size_t)(t + 1) * 16 * EDIM, EDIM, tid);
            ld_direct(vB, Bg + (size_t)(t + 1) * 16 * DDIM, DDIM, tid);
        }
        int s = t & 1;
        step16(S[s][0], S[s][1], S[s][2], S[s][3], acc, warpM, warpN);
        if (t + 1 < NK) {
            int s2 = (t + 1) & 1;
            st_direct(S[s2][0], S[s2][1], vA, 16.0f, tid);
            st_direct(S[s2][2], S[s2][3], vB, 1.0f, tid);
        }
        __syncthreads();
    }

    float* C = g_kv + (size_t)b * EDIM * DDIM;
#pragma unroll
    for (int mi = 0; mi < 4; mi++)
#pragma unroll
        for (int nj = 0; nj < 2; nj++)
            wmma::store_matrix_sync(
                C + (size_t)(mBase + warpM * 64 + mi * 16) * DDIM
                  + nBase + warpN * 32 + nj * 16,
                acc[mi][nj], DDIM, wmma::mem_row_major);
}

// ---------------------------------------------------------------------------
// Kernel 4: num. grid (DDIM/128, LSEQ/128, BATCH).  out = (16 q''Z) @ g_kv.
// ---------------------------------------------------------------------------
__global__ __launch_bounds__(256, 1) void num_kernel(float* __restrict__ out)
{
    DECL_SMEM;
    const int tid = threadIdx.x;
    const int warpM = (tid >> 5) >> 2, warpN = (tid >> 5) & 3;
    const int b = blockIdx.z;
    const int mBase = blockIdx.y * 128;   // l
    const int nBase = blockIdx.x * 128;   // d
    const float* Ag = g_q  + ((size_t)b * LSEQ + mBase) * EDIM;  // [l][e] trans
    const float* Bg = g_kv + (size_t)b * EDIM * DDIM + nBase;    // [e][d] direct

    wmma::fragment<wmma::accumulator, 16, 16, 16, float> acc[4][2];
#pragma unroll
    for (int mi = 0; mi < 4; mi++)
#pragma unroll
        for (int nj = 0; nj < 2; nj++) wmma::fill_fragment(acc[mi][nj], 0.0f);

    const int NK = EDIM / 16;
    float4 vA[2], vB[2];
    ld_trans(vA, Ag, EDIM, tid);
    ld_direct(vB, Bg, DDIM, tid);
    st_trans(S[0][0], S[0][1], vA, 16.0f, tid);
    st_direct(S[0][2], S[0][3], vB, 1.0f, tid);
    __syncthreads();
    for (int t = 0; t < NK; t++) {
        if (t + 1 < NK) {
            ld_trans(vA, Ag + (t + 1) * 16, EDIM, tid);
            ld_direct(vB, Bg + (size_t)(t + 1) * 16 * DDIM, DDIM, tid);
        }
        int s = t & 1;
        step16(S[s][0], S[s][1], S[s][2], S[s][3], acc, warpM, warpN);
        if (t + 1 < NK) {
            int s2 = (t + 1) & 1;
            st_trans(S[s2][0], S[s2][1], vA, 16.0f, tid);
            st_direct(S[s2][2], S[s2][3], vB, 1.0f, tid);
        }
        __syncthreads();
    }

    float* O = out + (size_t)b * LSEQ * DDIM;
#pragma unroll
    for (int mi = 0; mi < 4; mi++)
#pragma unroll
        for (int nj = 0; nj < 2; nj++)
            wmma::store_matrix_sync(
                O + (size_t)(mBase + warpM * 64 + mi * 16) * DDIM
                  + nBase + warpN * 32 + nj * 16,
                acc[mi][nj], DDIM, wmma::mem_row_major);
}

// ---------------------------------------------------------------------------
extern "C" void kernel_launch(void* const* d_in, const int* in_sizes, int n_in,
                              void* d_out, int out_size)
{
    const float* x  = (const float*)d_in[0];
    const float* qw = (const float*)d_in[1];
    const float* kw = (const float*)d_in[2];
    float* out = (float*)d_out;

    proj_kernel<<<dim3(EDIM / 128, BL / 128, 2), 256>>>(x, qw, kw);
    zinv_kernel<<<BL / 8, 256>>>();
    kv_kernel<<<dim3(DDIM / 128, EDIM / 128, BATCH), 256>>>(x);
    num_kernel<<<dim3(DDIM / 128, LSEQ / 128, BATCH), 256>>>(out);
}